// round 1
// baseline (speedup 1.0000x reference)
#include <cuda_runtime.h>
#include <cfloat>

// Problem constants (fixed by setup_inputs): xp (32, 64, 64, 512) fp32, NHWC-style
// layout x[b][r][c][m], m innermost. Output (32, 8*6*512): out[b][(iw*6+ih)*512 + m].
// Resize is identity (64 >= bins). Bin edges:
//   rows: iw*8 .. iw*8+8
//   cols: {0,11,21,32,43,53,64}  (round-half-even of i*64/6)

#define B_DIM 32
#define W_DIM 64
#define H_DIM 64
#define M_DIM 512
#define W_BINS 8
#define H_BINS 6
#define M4 (M_DIM / 4)   // 128 float4 per (b,r,c)

__constant__ int C_EDGE[H_BINS + 1] = {0, 11, 21, 32, 43, 53, 64};

static __device__ __forceinline__ float4 fmax4(float4 a, float4 b) {
    a.x = fmaxf(a.x, b.x);
    a.y = fmaxf(a.y, b.y);
    a.z = fmaxf(a.z, b.z);
    a.w = fmaxf(a.w, b.w);
    return a;
}

// One block per (batch, bin). 128 threads; thread t owns channels [4t, 4t+4).
// Per (r,c) the block loads 128 * 16B = 2KB contiguous -> fully coalesced.
__global__ __launch_bounds__(M4, 8)
void adaptive_maxpool_kernel(const float4* __restrict__ x4, float4* __restrict__ out4) {
    const int bin = blockIdx.x;       // 0..47  (iw*6 + ih)
    const int b   = blockIdx.y;       // 0..31
    const int iw  = bin / H_BINS;
    const int ih  = bin - iw * H_BINS;

    const int r1 = iw * (W_DIM / W_BINS);          // 8 rows per bin, always
    const int c1 = C_EDGE[ih];
    const int nc = C_EDGE[ih + 1] - c1;            // 10 or 11

    const int t = threadIdx.x;                     // 0..127
    const float4* base =
        x4 + ((size_t)(b * W_DIM + r1) * H_DIM + c1) * M4 + t;

    float4 acc = make_float4(-FLT_MAX, -FLT_MAX, -FLT_MAX, -FLT_MAX);

    if (nc == 11) {
        for (int r = 0; r < 8; ++r) {
            const float4* row = base + (size_t)r * (H_DIM * M4);
            #pragma unroll
            for (int c = 0; c < 11; ++c) {
                acc = fmax4(acc, __ldg(row + (size_t)c * M4));
            }
        }
    } else {
        for (int r = 0; r < 8; ++r) {
            const float4* row = base + (size_t)r * (H_DIM * M4);
            #pragma unroll
            for (int c = 0; c < 10; ++c) {
                acc = fmax4(acc, __ldg(row + (size_t)c * M4));
            }
        }
    }

    out4[((size_t)b * (W_BINS * H_BINS) + bin) * M4 + t] = acc;
}

extern "C" void kernel_launch(void* const* d_in, const int* in_sizes, int n_in,
                              void* d_out, int out_size) {
    (void)in_sizes; (void)n_in; (void)out_size;
    const float4* x4 = (const float4*)d_in[0];
    float4* o4 = (float4*)d_out;

    dim3 grid(W_BINS * H_BINS, B_DIM);   // (48, 32)
    adaptive_maxpool_kernel<<<grid, M4>>>(x4, o4);
}